// round 10
// baseline (speedup 1.0000x reference)
#include <cuda_runtime.h>

#define NQ       6
#define NPARAMS  15
#define NTHREADS 512
#define NWARPS   16
#define GRIDX    152
#define NROWS    16384
#define NCOLS    4096

typedef unsigned long long u64;

__device__ __forceinline__ u64 pack2(float lo, float hi) {
    u64 r; asm("mov.b64 %0, {%1, %2};" : "=l"(r) : "f"(lo), "f"(hi)); return r;
}
__device__ __forceinline__ u64 bcast2(float v) {
    u64 r; asm("mov.b64 %0, {%1, %1};" : "=l"(r) : "f"(v)); return r;
}
__device__ __forceinline__ void fma2(u64& d, u64 a, u64 b) {
    asm("fma.rn.f32x2 %0, %1, %2, %0;" : "+l"(d) : "l"(a), "l"(b));
}
__device__ __forceinline__ void unpack2(u64 v, float& lo, float& hi) {
    asm("mov.b64 {%0, %1}, %2;" : "=f"(lo), "=f"(hi) : "l"(v));
}

__global__ __launch_bounds__(NTHREADS, 1)
void fused_hybrid_kernel(const float* __restrict__ x,
                         const float* __restrict__ W1,
                         const float* __restrict__ b1,
                         const float* __restrict__ qw,
                         const float* __restrict__ W2,
                         const float* __restrict__ b2,
                         float* __restrict__ out)
{
    __shared__ float sR[NQ][NQ];        // composed 6x6 Givens product
    __shared__ float sW2[NQ];
    __shared__ float sB1[NQ];
    __shared__ float sMisc[2];          // [0]=b2, [1]=sum(W2)
    __shared__ float sPart[2][NWARPS][8];

    const int tid  = threadIdx.x;
    const int lane = tid & 31;
    const int warp = tid >> 5;

    // ---- one-time per-block: fold the 15 RBS gates into a 6x6 matrix ----
    if (tid == 0) {
        const int qs[NPARAMS] = {4,3,2,4,1,3,0,2,4,1,3,2,4,3,4};
        float M[NQ][NQ];
        #pragma unroll
        for (int i = 0; i < NQ; i++)
            #pragma unroll
            for (int j = 0; j < NQ; j++)
                M[i][j] = (i == j) ? 1.0f : 0.0f;
        #pragma unroll
        for (int k = 0; k < NPARAMS; k++) {
            float s, c;
            sincosf(qw[k], &s, &c);
            const int q = qs[k];
            #pragma unroll
            for (int j = 0; j < NQ; j++) {
                float a0 = M[q][j], a1 = M[q + 1][j];
                M[q][j]     =  c * a0 + s * a1;
                M[q + 1][j] = -s * a0 + c * a1;
            }
        }
        float sw = 0.0f;
        #pragma unroll
        for (int j = 0; j < NQ; j++) {
            #pragma unroll
            for (int i = 0; i < NQ; i++) sR[j][i] = M[j][i];
            float w2v = W2[j];
            sW2[j] = w2v;
            sw += w2v;
            sB1[j] = b1[j];
        }
        sMisc[0] = b2[0];
        sMisc[1] = sw;
    }

    // ---- load this thread's 8x6 slice of W1 into registers, pack as f32x2 ----
    const float4* __restrict__ W14 = reinterpret_cast<const float4*>(W1);
    float w[48];
    #pragma unroll
    for (int f = 0; f < 6; f++) {                 // chunk A: cols 4t..4t+3
        float4 v = W14[6 * tid + f];
        w[4 * f + 0] = v.x; w[4 * f + 1] = v.y;
        w[4 * f + 2] = v.z; w[4 * f + 3] = v.w;
    }
    #pragma unroll
    for (int f = 0; f < 6; f++) {                 // chunk B: cols 2048+4t..
        float4 v = W14[3072 + 6 * tid + f];
        w[24 + 4 * f + 0] = v.x; w[24 + 4 * f + 1] = v.y;
        w[24 + 4 * f + 2] = v.z; w[24 + 4 * f + 3] = v.w;
    }
    u64 wp[8][3];
    #pragma unroll
    for (int dl = 0; dl < 8; dl++)
        #pragma unroll
        for (int p = 0; p < 3; p++)
            wp[dl][p] = pack2(w[dl * 6 + 2 * p], w[dl * 6 + 2 * p + 1]);

    __syncthreads();

    const float4* __restrict__ x4 = reinterpret_cast<const float4*>(x);

    // ---- 2-deep register prefetch pipeline over rows ----
    int row = blockIdx.x;
    float4 xa1, xb1, xa2, xb2;
    {
        const float4* p = x4 + (long)row * 1024;
        xa1 = p[tid]; xb1 = p[tid + 512];
    }
    {
        int r2 = row + GRIDX;
        if (r2 < NROWS) {
            const float4* p = x4 + (long)r2 * 1024;
            xa2 = p[tid]; xb2 = p[tid + 512];
        }
    }

    for (int it = 0; row < NROWS; row += GRIDX, ++it) {
        float4 xa = xa1, xb = xb1;
        xa1 = xa2; xb1 = xb2;
        int r2 = row + 2 * GRIDX;
        if (r2 < NROWS) {
            const float4* p = x4 + (long)r2 * 1024;
            xa2 = p[tid]; xb2 = p[tid + 512];
        }

        // ---- 48 FMAs as 24 packed fma.rn.f32x2 ----
        u64 acc[3] = {0ull, 0ull, 0ull};
        {
            float xs[4] = {xa.x, xa.y, xa.z, xa.w};
            #pragma unroll
            for (int dl = 0; dl < 4; dl++) {
                u64 xv = bcast2(xs[dl]);
                fma2(acc[0], xv, wp[dl][0]);
                fma2(acc[1], xv, wp[dl][1]);
                fma2(acc[2], xv, wp[dl][2]);
            }
        }
        {
            float xs[4] = {xb.x, xb.y, xb.z, xb.w};
            #pragma unroll
            for (int dl = 0; dl < 4; dl++) {
                u64 xv = bcast2(xs[dl]);
                fma2(acc[0], xv, wp[4 + dl][0]);
                fma2(acc[1], xv, wp[4 + dl][1]);
                fma2(acc[2], xv, wp[4 + dl][2]);
            }
        }

        // ---- warp reduce 6 partial sums ----
        float s[6];
        unpack2(acc[0], s[0], s[1]);
        unpack2(acc[1], s[2], s[3]);
        unpack2(acc[2], s[4], s[5]);
        #pragma unroll
        for (int o = 16; o > 0; o >>= 1) {
            #pragma unroll
            for (int j = 0; j < NQ; j++)
                s[j] += __shfl_down_sync(0xffffffffu, s[j], o);
        }
        if (lane == 0) {
            #pragma unroll
            for (int j = 0; j < NQ; j++)
                sPart[it & 1][warp][j] = s[j];
        }
        __syncthreads();

        // ---- finalize (rotating warp so the serial tail amortizes) ----
        if (tid == ((it & 15) << 5)) {
            float h[NQ];
            #pragma unroll
            for (int j = 0; j < NQ; j++) h[j] = sB1[j];
            #pragma unroll
            for (int wdx = 0; wdx < NWARPS; wdx++)
                #pragma unroll
                for (int j = 0; j < NQ; j++)
                    h[j] += sPart[it & 1][wdx][j];

            float ss = 0.0f;
            #pragma unroll
            for (int j = 0; j < NQ; j++) ss += h[j] * h[j];

            // g = R h ;  z.W2 = sum(W2) - 2 * sum(W2_j g_j^2) / ||h||^2
            float dw = 0.0f;
            #pragma unroll
            for (int j = 0; j < NQ; j++) {
                float g = 0.0f;
                #pragma unroll
                for (int i = 0; i < NQ; i++) g = fmaf(sR[j][i], h[i], g);
                dw = fmaf(sW2[j], g * g, dw);
            }
            // ss == 0 -> reference yields NaN z, guarded to 0 -> logit = b2
            float t = (ss > 0.0f) ? (sMisc[0] + sMisc[1] - 2.0f * dw / ss)
                                  : sMisc[0];
            out[row] = 1.0f / (1.0f + __expf(-t));
        }
    }
}

extern "C" void kernel_launch(void* const* d_in, const int* in_sizes, int n_in,
                              void* d_out, int out_size) {
    const float* x  = (const float*)d_in[0];
    const float* W1 = (const float*)d_in[1];
    const float* b1 = (const float*)d_in[2];
    const float* qw = (const float*)d_in[3];
    const float* W2 = (const float*)d_in[4];
    const float* b2 = (const float*)d_in[5];
    float* out = (float*)d_out;

    fused_hybrid_kernel<<<GRIDX, NTHREADS>>>(x, W1, b1, qw, W2, b2, out);
}

// round 11
// speedup vs baseline: 1.0027x; 1.0027x over previous
#include <cuda_runtime.h>

#define NQ       6
#define NPARAMS  15
#define NTHREADS 512
#define NWARPS   16
#define GRIDX    152
#define NROWS    16384
#define NCOLS    4096

typedef unsigned long long u64;

__device__ __forceinline__ u64 pack2(float lo, float hi) {
    u64 r; asm("mov.b64 %0, {%1, %2};" : "=l"(r) : "f"(lo), "f"(hi)); return r;
}
__device__ __forceinline__ u64 bcast2(float v) {
    u64 r; asm("mov.b64 %0, {%1, %1};" : "=l"(r) : "f"(v)); return r;
}
__device__ __forceinline__ void fma2(u64& d, u64 a, u64 b) {
    asm("fma.rn.f32x2 %0, %1, %2, %0;" : "+l"(d) : "l"(a), "l"(b));
}
__device__ __forceinline__ void unpack2(u64 v, float& lo, float& hi) {
    asm("mov.b64 {%0, %1}, %2;" : "=f"(lo), "=f"(hi) : "l"(v));
}

__global__ __launch_bounds__(NTHREADS, 1)
void fused_hybrid_kernel(const float* __restrict__ x,
                         const float* __restrict__ W1,
                         const float* __restrict__ b1,
                         const float* __restrict__ qw,
                         const float* __restrict__ W2,
                         const float* __restrict__ b2,
                         float* __restrict__ out)
{
    __shared__ float sR[NQ][NQ];        // composed 6x6 Givens product
    __shared__ float sW2[NQ];
    __shared__ float sB1[NQ];
    __shared__ float sMisc[2];          // [0]=b2, [1]=sum(W2)
    __shared__ float sPart[2][NWARPS][8];

    const int tid  = threadIdx.x;
    const int lane = tid & 31;
    const int warp = tid >> 5;

    // ---- one-time per-block: fold the 15 RBS gates into a 6x6 matrix ----
    if (tid == 0) {
        const int qs[NPARAMS] = {4,3,2,4,1,3,0,2,4,1,3,2,4,3,4};
        float M[NQ][NQ];
        #pragma unroll
        for (int i = 0; i < NQ; i++)
            #pragma unroll
            for (int j = 0; j < NQ; j++)
                M[i][j] = (i == j) ? 1.0f : 0.0f;
        #pragma unroll
        for (int k = 0; k < NPARAMS; k++) {
            float s, c;
            sincosf(qw[k], &s, &c);
            const int q = qs[k];
            #pragma unroll
            for (int j = 0; j < NQ; j++) {
                float a0 = M[q][j], a1 = M[q + 1][j];
                M[q][j]     =  c * a0 + s * a1;
                M[q + 1][j] = -s * a0 + c * a1;
            }
        }
        float sw = 0.0f;
        #pragma unroll
        for (int j = 0; j < NQ; j++) {
            #pragma unroll
            for (int i = 0; i < NQ; i++) sR[j][i] = M[j][i];
            float w2v = W2[j];
            sW2[j] = w2v;
            sw += w2v;
            sB1[j] = b1[j];
        }
        sMisc[0] = b2[0];
        sMisc[1] = sw;
    }

    // ---- load this thread's 8x6 slice of W1 into registers, pack as f32x2 ----
    const float4* __restrict__ W14 = reinterpret_cast<const float4*>(W1);
    float w[48];
    #pragma unroll
    for (int f = 0; f < 6; f++) {                 // chunk A: cols 4t..4t+3
        float4 v = W14[6 * tid + f];
        w[4 * f + 0] = v.x; w[4 * f + 1] = v.y;
        w[4 * f + 2] = v.z; w[4 * f + 3] = v.w;
    }
    #pragma unroll
    for (int f = 0; f < 6; f++) {                 // chunk B: cols 2048+4t..
        float4 v = W14[3072 + 6 * tid + f];
        w[24 + 4 * f + 0] = v.x; w[24 + 4 * f + 1] = v.y;
        w[24 + 4 * f + 2] = v.z; w[24 + 4 * f + 3] = v.w;
    }
    u64 wp[8][3];
    #pragma unroll
    for (int dl = 0; dl < 8; dl++)
        #pragma unroll
        for (int p = 0; p < 3; p++)
            wp[dl][p] = pack2(w[dl * 6 + 2 * p], w[dl * 6 + 2 * p + 1]);

    __syncthreads();

    const float4* __restrict__ x4 = reinterpret_cast<const float4*>(x);

    // ---- 2-deep register prefetch pipeline over rows ----
    int row = blockIdx.x;
    float4 xa1, xb1, xa2, xb2;
    {
        const float4* p = x4 + (long)row * 1024;
        xa1 = p[tid]; xb1 = p[tid + 512];
    }
    {
        int r2 = row + GRIDX;
        if (r2 < NROWS) {
            const float4* p = x4 + (long)r2 * 1024;
            xa2 = p[tid]; xb2 = p[tid + 512];
        }
    }

    for (int it = 0; row < NROWS; row += GRIDX, ++it) {
        float4 xa = xa1, xb = xb1;
        xa1 = xa2; xb1 = xb2;
        int r2 = row + 2 * GRIDX;
        if (r2 < NROWS) {
            const float4* p = x4 + (long)r2 * 1024;
            xa2 = p[tid]; xb2 = p[tid + 512];
        }

        // ---- 48 FMAs as 24 packed fma.rn.f32x2 ----
        u64 acc[3] = {0ull, 0ull, 0ull};
        {
            float xs[4] = {xa.x, xa.y, xa.z, xa.w};
            #pragma unroll
            for (int dl = 0; dl < 4; dl++) {
                u64 xv = bcast2(xs[dl]);
                fma2(acc[0], xv, wp[dl][0]);
                fma2(acc[1], xv, wp[dl][1]);
                fma2(acc[2], xv, wp[dl][2]);
            }
        }
        {
            float xs[4] = {xb.x, xb.y, xb.z, xb.w};
            #pragma unroll
            for (int dl = 0; dl < 4; dl++) {
                u64 xv = bcast2(xs[dl]);
                fma2(acc[0], xv, wp[4 + dl][0]);
                fma2(acc[1], xv, wp[4 + dl][1]);
                fma2(acc[2], xv, wp[4 + dl][2]);
            }
        }

        // ---- warp reduce 6 partial sums ----
        float s[6];
        unpack2(acc[0], s[0], s[1]);
        unpack2(acc[1], s[2], s[3]);
        unpack2(acc[2], s[4], s[5]);
        #pragma unroll
        for (int o = 16; o > 0; o >>= 1) {
            #pragma unroll
            for (int j = 0; j < NQ; j++)
                s[j] += __shfl_down_sync(0xffffffffu, s[j], o);
        }
        if (lane == 0) {
            #pragma unroll
            for (int j = 0; j < NQ; j++)
                sPart[it & 1][warp][j] = s[j];
        }
        __syncthreads();

        // ---- finalize (rotating warp so the serial tail amortizes) ----
        if (tid == ((it & 15) << 5)) {
            float h[NQ];
            #pragma unroll
            for (int j = 0; j < NQ; j++) h[j] = sB1[j];
            #pragma unroll
            for (int wdx = 0; wdx < NWARPS; wdx++)
                #pragma unroll
                for (int j = 0; j < NQ; j++)
                    h[j] += sPart[it & 1][wdx][j];

            float ss = 0.0f;
            #pragma unroll
            for (int j = 0; j < NQ; j++) ss += h[j] * h[j];

            // g = R h ;  z.W2 = sum(W2) - 2 * sum(W2_j g_j^2) / ||h||^2
            float dw = 0.0f;
            #pragma unroll
            for (int j = 0; j < NQ; j++) {
                float g = 0.0f;
                #pragma unroll
                for (int i = 0; i < NQ; i++) g = fmaf(sR[j][i], h[i], g);
                dw = fmaf(sW2[j], g * g, dw);
            }
            // ss == 0 -> reference yields NaN z, guarded to 0 -> logit = b2
            float t = (ss > 0.0f) ? (sMisc[0] + sMisc[1] - 2.0f * dw / ss)
                                  : sMisc[0];
            out[row] = 1.0f / (1.0f + __expf(-t));
        }
    }
}

extern "C" void kernel_launch(void* const* d_in, const int* in_sizes, int n_in,
                              void* d_out, int out_size) {
    const float* x  = (const float*)d_in[0];
    const float* W1 = (const float*)d_in[1];
    const float* b1 = (const float*)d_in[2];
    const float* qw = (const float*)d_in[3];
    const float* W2 = (const float*)d_in[4];
    const float* b2 = (const float*)d_in[5];
    float* out = (float*)d_out;

    fused_hybrid_kernel<<<GRIDX, NTHREADS>>>(x, W1, b1, qw, W2, b2, out);
}